// round 11
// baseline (speedup 1.0000x reference)
#include <cuda_runtime.h>
#include <math.h>

#define B_ 2
#define M_ 384
#define N_ 384

// Shared-memory layout (float offsets)
#define OFF_S     0        // 8 copies * 640 = 5120
#define OFF_CW    5120     // 384 * float4 corner weights = 1536
#define OFF_CPK   6656     // 384 ints (n<<8 | y0<<4 | (x0+1))
#define OFF_STOT  7040     // 640  [h(10)][w(4)][comp(16)]
#define OFF_RED   7680     // 8 (psi warp partials)
#define OFF_PSI   7688     // 1
#define SMEM_FLOATS 7692
#define SMEM_BYTES  (SMEM_FLOATS * 4)   // 30768 B -> 6 blocks/SM

__global__ __launch_bounds__(256, 6)
void equi_cts_conv_kernel(const float* __restrict__ field,
                          const float* __restrict__ center,
                          const float* __restrict__ feat,
                          const float* __restrict__ mask,
                          const float* __restrict__ kern,
                          float* __restrict__ out)
{
    extern __shared__ float sm[];
    float*  S     = sm + OFF_S;
    float4* cw4   = (float4*)(sm + OFF_CW);
    int*    cpk   = (int*)(sm + OFF_CPK);
    float*  Stot  = sm + OFF_STOT;
    float*  red   = sm + OFF_RED;
    float*  shpsi = sm + OFF_PSI;
    __shared__ int wcnt[16];

    const int tid  = threadIdx.x;
    const int lane = tid & 31;
    const int warp = tid >> 5;
    const int bm   = blockIdx.x;
    const int b    = bm / M_;

    const float cx = center[bm * 2 + 0];
    const float cy = center[bm * 2 + 1];

    // ---------- Phase 0: zero S copies ----------
    {
        float4 z = make_float4(0.f, 0.f, 0.f, 0.f);
        float4* S4 = (float4*)S;
        #pragma unroll
        for (int i = tid; i < 1280; i += 256) S4[i] = z;
    }

    // ---------- Phase A1: geometry + corner weights + ballots ----------
    float psi_part = 0.f;
    unsigned ballots[2];
    float4 a_cw[2];
    int    a_pk[2];
    bool   a_act[2];
    #pragma unroll
    for (int r = 0; r < 2; ++r) {
        int n = r * 256 + tid;
        bool act = false;
        float4 cwv = make_float4(0.f, 0.f, 0.f, 0.f);
        int pack = 0;
        if (n < N_) {
            float2 fp = *(const float2*)(field + ((size_t)b * N_ + n) * 2);
            float relx = (fp.x - cx) * (1.0f / 1.5f);
            float rely = (fp.y - cy) * (1.0f / 1.5f);
            float r2 = relx * relx + rely * rely;
            float s  = 1.0f - r2;
            if (s > 0.0f) {
                float att = s * s * s * mask[(size_t)b * N_ + n];
                float rr;
                asm("sqrt.approx.f32 %0, %1;" : "=f"(rr) : "f"(r2 + 1e-9f));
                // ---- theta/pi via octant-reduced poly (replaces atan2f) ----
                float ax = fabsf(relx), ay = fabsf(rely);
                float mx = fmaxf(ax, ay), mn = fminf(ax, ay);
                float z  = (mx > 0.0f) ? __fdividef(mn, mx) : 0.0f;
                float z2 = z * z;
                float q = -0.0037310f;
                q = fmaf(q, z2,  0.0167600f);
                q = fmaf(q, z2, -0.0370620f);
                q = fmaf(q, z2,  0.0616061f);
                q = fmaf(q, z2, -0.1058772f);
                q = fmaf(q, z2,  0.3183026478f);
                q = q * z;                          // atan(z)/pi
                if (ay > ax)       q = 0.5f - q;
                if (relx < 0.0f)   q = 1.0f - q;
                q = copysignf(q, rely);             // theta/pi in [-1,1]
                // ------------------------------------------------------------
                float ix = 4.0f * rr - 0.5f;        // ((gx+1)*W-1)/2, W=4
                float iy = fmaf(4.0f, q, 4.5f);     // 4.5 + 5*(0.8*q), H=10
                float x0f = floorf(ix), y0f = floorf(iy);
                float wx = ix - x0f;
                float wy = iy - y0f;
                int x0 = (int)x0f, y0 = (int)y0f;   // x0 in [-1,3], y0 in [0,8]
                float omx = 1.0f - wx, omy = 1.0f - wy;
                cwv.x = att * omx * omy;
                cwv.y = att * wx  * omy;
                cwv.z = att * omx * wy;
                cwv.w = att * wx  * wy;
                pack = ((x0 + 1) | (y0 << 4)) | (n << 8);
                psi_part += att;
                act = (att != 0.0f);
            }
        }
        a_cw[r] = cwv; a_pk[r] = pack; a_act[r] = act;
        ballots[r] = __ballot_sync(0xffffffffu, act);
        if (lane == 0) wcnt[r * 8 + warp] = __popc(ballots[r]);
    }

    // psi warp-reduce
    #pragma unroll
    for (int o = 16; o; o >>= 1) psi_part += __shfl_xor_sync(0xffffffffu, psi_part, o);
    if (lane == 0) red[warp] = psi_part;
    __syncthreads();   // covers S-zeroing, wcnt, red

    // ---------- Phase A2: deterministic prefix + compacted write ----------
    int nact;
    {
        int tot = 0, base0 = 0, base1 = 0;
        #pragma unroll
        for (int s2 = 0; s2 < 16; ++s2) {
            if (s2 == warp)     base0 = tot;
            if (s2 == warp + 8) base1 = tot;
            tot += wcnt[s2];
        }
        nact = tot;
        unsigned lt = (1u << lane) - 1u;
        if (a_act[0]) {
            int idx = base0 + __popc(ballots[0] & lt);
            cw4[idx] = a_cw[0]; cpk[idx] = a_pk[0];
        }
        if (a_act[1]) {
            int idx = base1 + __popc(ballots[1] & lt);
            cw4[idx] = a_cw[1]; cpk[idx] = a_pk[1];
        }
        if (tid == 0) {
            float p = 0.f;
            #pragma unroll
            for (int w = 0; w < 8; ++w) p += red[w];
            shpsi[0] = (p == 0.0f) ? 1.0f : p;
        }
    }
    __syncthreads();

    // ---------- Phase B: branchless scatter; one n per warp-iter (R9 form) ----------
    // lane = corner(2b)*8 + pairi(3b); 32 lanes hit 32 distinct smem addrs
    // (corner cells adjacent-mod-4 in xi even under clamping). Non-divergent
    // straight-line body -> cross-iteration RMW ordering holds without syncwarp;
    // ptxas pipelines next-iteration loads over the current RMW.
    {
        const int corner = lane >> 3;
        const int pairi  = lane & 7;
        const int cbx = corner & 1;
        const int cby = corner >> 1;
        float* Smine = S + warp * 640;
        const float* cwf = (const float*)cw4;
        const float* featB = feat + (size_t)b * N_ * 16;

        for (int k = warp; k < nact; k += 8) {
            float A  = cwf[k * 4 + corner];      // multicast LDS.32
            int   pk = cpk[k];                   // broadcast
            int xi = (pk & 15) - 1 + cbx;        // -1..4
            int yi = ((pk >> 4) & 15) + cby;     // 0..9
            bool ok = (unsigned)xi <= 3u;
            xi &= 3;
            A = ok ? A : 0.0f;
            int foff = ((pk >> 4) & ~15) + pairi * 2;   // n*16 + pairi*2
            float2 f = __ldg((const float2*)(featB + foff));
            float* sp = Smine + (yi * 4 + xi) * 16 + pairi * 2;
            float2 sv = *(float2*)sp;
            sv.x = fmaf(A, f.x, sv.x);
            sv.y = fmaf(A, f.y, sv.y);
            *(float2*)sp = sv;
        }
    }
    __syncthreads();

    // ---------- Phase C1: reduce 8 S copies (float4) ----------
    {
        const float4* S4 = (const float4*)S;
        float4* Stot4 = (float4*)Stot;
        for (int e = tid; e < 160; e += 256) {
            float4 a = S4[e];
            #pragma unroll
            for (int c = 1; c < 8; ++c) {
                float4 v = S4[c * 160 + e];
                a.x += v.x; a.y += v.y; a.z += v.z; a.w += v.w;
            }
            Stot4[e] = a;
        }
    }
    __syncthreads();

    // ---------- Phase C2: out[o,y] = sum kern[o,i,w,t,y,x] * wrapped Stot ----------
    // warp = o; lane = w*8 + i. kern: 8x LDG.128 per lane (L1-resident).
    // Theta-wrap folded in-register: h = t+1, plus h=9 at t=0 and h=0 at t=7.
    // Stot LDS.64 at (h*4+w)*16 + i*2: lanes span 64 consecutive floats -> conflict-free.
    {
        const int w = lane >> 3;
        const int i = lane & 7;
        const float4* kb4 = (const float4*)(kern + warp * 1024 + i * 128 + w * 32);
        const float2* St2 = (const float2*)Stot;
        float acc0 = 0.f, acc1 = 0.f;
        #pragma unroll
        for (int t = 0; t < 8; ++t) {
            float4 kv = __ldg(kb4 + t);                    // (y0x0, y0x1, y1x0, y1x1)
            float2 sf = St2[((t + 1) * 4 + w) * 8 + i];    // h = t+1
            if (t == 0) {
                float2 u = St2[(9 * 4 + w) * 8 + i];       // h = 9 wraps onto t=0
                sf.x += u.x; sf.y += u.y;
            }
            if (t == 7) {
                float2 u = St2[(0 * 4 + w) * 8 + i];       // h = 0 wraps onto t=7
                sf.x += u.x; sf.y += u.y;
            }
            acc0 = fmaf(kv.x, sf.x, fmaf(kv.y, sf.y, acc0));
            acc1 = fmaf(kv.z, sf.x, fmaf(kv.w, sf.y, acc1));
        }
        #pragma unroll
        for (int o = 16; o; o >>= 1) {
            acc0 += __shfl_xor_sync(0xffffffffu, acc0, o);
            acc1 += __shfl_xor_sync(0xffffffffu, acc1, o);
        }
        if (lane == 0) {
            float inv = 1.0f / shpsi[0];
            *(float2*)(out + bm * 16 + warp * 2) = make_float2(acc0 * inv, acc1 * inv);
        }
    }
}

extern "C" void kernel_launch(void* const* d_in, const int* in_sizes, int n_in,
                              void* d_out, int out_size)
{
    const float* field  = (const float*)d_in[0];
    const float* center = (const float*)d_in[1];
    const float* feat   = (const float*)d_in[2];
    const float* mask   = (const float*)d_in[3];
    const float* kern   = (const float*)d_in[4];
    float* out = (float*)d_out;

    cudaFuncSetAttribute(equi_cts_conv_kernel,
                         cudaFuncAttributeMaxDynamicSharedMemorySize, SMEM_BYTES);
    equi_cts_conv_kernel<<<B_ * M_, 256, SMEM_BYTES>>>(field, center, feat, mask, kern, out);
}

// round 12
// speedup vs baseline: 1.1806x; 1.1806x over previous
#include <cuda_runtime.h>
#include <math.h>

#define B_ 2
#define M_ 384
#define N_ 384

// Shared-memory layout (float offsets)
#define OFF_S     0        // 8 copies * 640 = 5120
#define OFF_CW    5120     // 384 * float4 corner weights = 1536
#define OFF_CPK   6656     // 384 ints (n<<8 | y0<<4 | xhi<<2 | xlo)
#define OFF_SFOLD 7040     // 16*33 = 528, padded [comp(16)][t*4+w (32, stride 33)]
#define OFF_RED   7568     // 8 (psi warp partials)
#define OFF_PSI   7576     // 1 (reciprocal)
#define SMEM_FLOATS 7580
#define SMEM_BYTES  (SMEM_FLOATS * 4)   // 30320 B -> 6 blocks/SM

__global__ __launch_bounds__(256, 6)
void equi_cts_conv_kernel(const float* __restrict__ field,
                          const float* __restrict__ center,
                          const float* __restrict__ feat,
                          const float* __restrict__ mask,
                          const float* __restrict__ kern,
                          float* __restrict__ out)
{
    extern __shared__ float sm[];
    float*  S     = sm + OFF_S;
    float4* cw4   = (float4*)(sm + OFF_CW);
    int*    cpk   = (int*)(sm + OFF_CPK);
    float*  Sfold = sm + OFF_SFOLD;
    float*  red   = sm + OFF_RED;
    float*  shpsi = sm + OFF_PSI;
    __shared__ int wcnt[16];

    const int tid  = threadIdx.x;
    const int lane = tid & 31;
    const int warp = tid >> 5;
    const int bm   = blockIdx.x;
    const int b    = bm / M_;

    const float cx = center[bm * 2 + 0];
    const float cy = center[bm * 2 + 1];

    // ---------- Phase 0: zero S copies ----------
    {
        float4 z = make_float4(0.f, 0.f, 0.f, 0.f);
        float4* S4 = (float4*)S;
        #pragma unroll
        for (int i = tid; i < 1280; i += 256) S4[i] = z;
    }

    // ---------- Phase A1: geometry + corner weights + ballots ----------
    float psi_part = 0.f;
    unsigned ballots[2];
    float4 a_cw[2];
    int    a_pk[2];
    bool   a_act[2];
    #pragma unroll
    for (int r = 0; r < 2; ++r) {
        int n = r * 256 + tid;
        bool act = false;
        float4 cwv = make_float4(0.f, 0.f, 0.f, 0.f);
        int pack = 0;
        if (n < N_) {
            float2 fp = *(const float2*)(field + ((size_t)b * N_ + n) * 2);
            float relx = (fp.x - cx) * (1.0f / 1.5f);
            float rely = (fp.y - cy) * (1.0f / 1.5f);
            float r2 = relx * relx + rely * rely;
            float s  = 1.0f - r2;
            if (s > 0.0f) {
                float att = s * s * s * mask[(size_t)b * N_ + n];
                float rr;
                asm("sqrt.approx.f32 %0, %1;" : "=f"(rr) : "f"(r2 + 1e-9f));
                // theta/pi via octant-reduced poly
                float ax = fabsf(relx), ay = fabsf(rely);
                float mx = fmaxf(ax, ay), mn = fminf(ax, ay);
                float z  = (mx > 0.0f) ? __fdividef(mn, mx) : 0.0f;
                float z2 = z * z;
                float q = -0.0037310f;
                q = fmaf(q, z2,  0.0167600f);
                q = fmaf(q, z2, -0.0370620f);
                q = fmaf(q, z2,  0.0616061f);
                q = fmaf(q, z2, -0.1058772f);
                q = fmaf(q, z2,  0.3183026478f);
                q = q * z;                          // atan(z)/pi
                if (ay > ax)       q = 0.5f - q;
                if (relx < 0.0f)   q = 1.0f - q;
                q = copysignf(q, rely);             // theta/pi in [-1,1]
                float ix = 4.0f * rr - 0.5f;        // W=4
                float iy = fmaf(4.0f, q, 4.5f);     // H=10
                float x0f = floorf(ix), y0f = floorf(iy);
                float wx = ix - x0f;
                float wy = iy - y0f;
                int x0 = (int)x0f, y0 = (int)y0f;   // x0 in [-1,3], y0 in [0,8]
                float omx = 1.0f - wx, omy = 1.0f - wy;
                cwv.x = att * omx * omy;
                cwv.y = att * wx  * omy;
                cwv.z = att * omx * wy;
                cwv.w = att * wx  * wy;
                // pre-clamp: edge corners get zero weight AND a distinct dummy cell
                int xlo = x0, xhi = x0 + 1;
                if (x0 < 0)  { cwv.x = 0.f; cwv.z = 0.f; xlo = 1; }   // xlo!=xhi(=0)
                if (x0 >= 3) { cwv.y = 0.f; cwv.w = 0.f; xhi = 2; }   // xhi!=xlo(=3)
                pack = xlo | (xhi << 2) | (y0 << 4) | (n << 8);
                psi_part += att;
                act = (att != 0.0f);
            }
        }
        a_cw[r] = cwv; a_pk[r] = pack; a_act[r] = act;
        ballots[r] = __ballot_sync(0xffffffffu, act);
        if (lane == 0) wcnt[r * 8 + warp] = __popc(ballots[r]);
    }

    // psi warp-reduce
    #pragma unroll
    for (int o = 16; o; o >>= 1) psi_part += __shfl_xor_sync(0xffffffffu, psi_part, o);
    if (lane == 0) red[warp] = psi_part;
    __syncthreads();   // covers S-zeroing, wcnt, red

    // ---------- Phase A2: deterministic prefix + compacted write ----------
    int nact;
    {
        int tot = 0, base0 = 0, base1 = 0;
        #pragma unroll
        for (int s2 = 0; s2 < 16; ++s2) {
            if (s2 == warp)     base0 = tot;
            if (s2 == warp + 8) base1 = tot;
            tot += wcnt[s2];
        }
        nact = tot;
        unsigned lt = (1u << lane) - 1u;
        if (a_act[0]) {
            int idx = base0 + __popc(ballots[0] & lt);
            cw4[idx] = a_cw[0]; cpk[idx] = a_pk[0];
        }
        if (a_act[1]) {
            int idx = base1 + __popc(ballots[1] & lt);
            cw4[idx] = a_cw[1]; cpk[idx] = a_pk[1];
        }
        if (tid == 0) {
            float p = 0.f;
            #pragma unroll
            for (int w = 0; w < 8; ++w) p += red[w];
            shpsi[0] = (p == 0.0f) ? 1.0f : 1.0f / p;   // store reciprocal
        }
    }
    __syncthreads();

    // ---------- Phase B: branchless scatter; one n per warp-iter ----------
    // lane = corner(2b)*8 + pairi(3b). Corner cells of one n are 4 distinct
    // (xlo != xhi by construction, y0 vs y0+1); edge corners carry A=0 into a
    // distinct dummy cell. Non-divergent body -> in-order per-warp smem RMW.
    {
        const int corner = lane >> 3;
        const int pairi  = lane & 7;
        const int xsh = (corner & 1) << 1;   // 0 for xlo, 2 for xhi
        const int cby = corner >> 1;
        float* Smine = S + warp * 640;
        const float* cwf = (const float*)cw4;
        const float* featB = feat + (size_t)b * N_ * 16;

        for (int k = warp; k < nact; k += 8) {
            float A  = cwf[k * 4 + corner];             // multicast LDS.32
            int   pk = cpk[k];                          // broadcast
            int xi = (pk >> xsh) & 3;
            int yi = ((pk >> 4) & 15) + cby;            // 0..9
            int foff = ((pk >> 4) & ~15) + pairi * 2;   // n*16 + pairi*2
            float2 f = __ldg((const float2*)(featB + foff));
            float* sp = Smine + (yi * 4 + xi) * 16 + pairi * 2;
            float2 sv = *(float2*)sp;
            sv.x = fmaf(A, f.x, sv.x);
            sv.y = fmaf(A, f.y, sv.y);
            *(float2*)sp = sv;
        }
    }
    __syncthreads();

    // ---------- Phase C1': reduce 8 copies + theta-wrap fold -> padded Sfold ----------
    // 256 threads, one float2 each: e = (t(8), w(4), cpair(8)).
    // Sfold[comp*33 + t*4 + w]; wrap rows h=9 -> t=0, h=0 -> t=7.
    {
        const float2* S2 = (const float2*)S;
        int e = tid;
        int cpair = e & 7;
        int w  = (e >> 3) & 3;
        int t  = e >> 5;
        int src = ((t + 1) * 4 + w) * 8 + cpair;
        float2 a = S2[src];
        #pragma unroll
        for (int c = 1; c < 8; ++c) {
            float2 v = S2[c * 320 + src];
            a.x += v.x; a.y += v.y;
        }
        if (t == 0) {
            int sw = (9 * 4 + w) * 8 + cpair;
            #pragma unroll
            for (int c = 0; c < 8; ++c) {
                float2 v = S2[c * 320 + sw];
                a.x += v.x; a.y += v.y;
            }
        }
        if (t == 7) {
            int sw = (0 * 4 + w) * 8 + cpair;
            #pragma unroll
            for (int c = 0; c < 8; ++c) {
                float2 v = S2[c * 320 + sw];
                a.x += v.x; a.y += v.y;
            }
        }
        int tw = t * 4 + w;
        Sfold[(cpair * 2 + 0) * 33 + tw] = a.x;
        Sfold[(cpair * 2 + 1) * 33 + tw] = a.y;
    }
    __syncthreads();

    // ---------- Phase C2: out[o,y] = sum kern[o,i,w,t,y,x] * Sfold[i,x][t,w] ----------
    // warp = o; lane = t*4 + y*2 + x. kern: 32 coalesced LDG.32 (1 line each).
    // Sfold LDS: addr = (2i+x)*33 + 4t + w -> banks (x+4t)%32: conflict-free.
    {
        const int t = lane >> 2;
        const int x = lane & 1;
        const float* kb = kern + warp * 1024;
        float acc = 0.f;
        #pragma unroll
        for (int i = 0; i < 8; ++i) {
            const float* sfr = Sfold + (i * 2 + x) * 33 + t * 4;
            #pragma unroll
            for (int w = 0; w < 4; ++w) {
                float kv = __ldg(kb + i * 128 + w * 32 + lane);
                acc = fmaf(kv, sfr[w], acc);
            }
        }
        // reduce over x (bit0) and t (bits 2..4); keep y (bit1) distinct
        acc += __shfl_xor_sync(0xffffffffu, acc, 1);
        acc += __shfl_xor_sync(0xffffffffu, acc, 4);
        acc += __shfl_xor_sync(0xffffffffu, acc, 8);
        acc += __shfl_xor_sync(0xffffffffu, acc, 16);
        if ((lane & ~2u) == 0) {   // lanes 0 (y=0) and 2 (y=1)
            out[bm * 16 + warp * 2 + (lane >> 1)] = acc * shpsi[0];
        }
    }
}

extern "C" void kernel_launch(void* const* d_in, const int* in_sizes, int n_in,
                              void* d_out, int out_size)
{
    const float* field  = (const float*)d_in[0];
    const float* center = (const float*)d_in[1];
    const float* feat   = (const float*)d_in[2];
    const float* mask   = (const float*)d_in[3];
    const float* kern   = (const float*)d_in[4];
    float* out = (float*)d_out;

    cudaFuncSetAttribute(equi_cts_conv_kernel,
                         cudaFuncAttributeMaxDynamicSharedMemorySize, SMEM_BYTES);
    equi_cts_conv_kernel<<<B_ * M_, 256, SMEM_BYTES>>>(field, center, feat, mask, kern, out);
}

// round 13
// speedup vs baseline: 1.3709x; 1.1612x over previous
#include <cuda_runtime.h>
#include <math.h>

#define B_ 2
#define M_ 384
#define N_ 384

// Shared-memory layout (float offsets)
#define OFF_S     0        // 8 copies * 640 = 5120
#define OFF_CW    5120     // 384 * float4 corner weights = 1536 (reused as Sfold in C)
#define OFF_CPK   6656     // 384 ints (n<<8 | y0<<4 | xhi<<2 | xlo)
#define OFF_SFOLD OFF_CW   // 528 floats, alias: cw4 dead after Phase B
#define OFF_RED   7040     // 8 (psi warp partials)
#define OFF_PSI   7048     // 1 (reciprocal)
#define SMEM_FLOATS 7052
#define SMEM_BYTES  (SMEM_FLOATS * 4)   // 28208 B -> 6 blocks/SM, L1D ~59KB

__global__ __launch_bounds__(256, 6)
void equi_cts_conv_kernel(const float* __restrict__ field,
                          const float* __restrict__ center,
                          const float* __restrict__ feat,
                          const float* __restrict__ mask,
                          const float* __restrict__ kern,
                          float* __restrict__ out)
{
    extern __shared__ float sm[];
    float*  S     = sm + OFF_S;
    float4* cw4   = (float4*)(sm + OFF_CW);
    int*    cpk   = (int*)(sm + OFF_CPK);
    float*  Sfold = sm + OFF_SFOLD;       // valid only after Phase-B barrier
    float*  red   = sm + OFF_RED;
    float*  shpsi = sm + OFF_PSI;
    __shared__ int wcnt[16];

    const int tid  = threadIdx.x;
    const int lane = tid & 31;
    const int warp = tid >> 5;
    const int bm   = blockIdx.x;
    const int b    = bm / M_;

    const float cx = center[bm * 2 + 0];
    const float cy = center[bm * 2 + 1];

    // ---------- Phase 0: zero S copies ----------
    {
        float4 z = make_float4(0.f, 0.f, 0.f, 0.f);
        float4* S4 = (float4*)S;
        #pragma unroll
        for (int i = tid; i < 1280; i += 256) S4[i] = z;
    }

    // ---------- Phase A1: geometry + corner weights + ballots ----------
    // Hoist both rounds' global loads for MLP on the cold-start burst.
    float2 fpv[2];
    float  mkv[2];
    {
        const float2* fB = (const float2*)(field + (size_t)b * N_ * 2);
        const float*  mB = mask + (size_t)b * N_;
        fpv[0] = fB[tid];
        fpv[1] = fB[256 + tid >= N_ ? tid : 256 + tid];   // round 1 may be out of range
        mkv[0] = mB[tid];
        mkv[1] = mB[256 + tid >= N_ ? tid : 256 + tid];
    }

    float psi_part = 0.f;
    unsigned ballots[2];
    float4 a_cw[2];
    int    a_pk[2];
    bool   a_act[2];
    #pragma unroll
    for (int r = 0; r < 2; ++r) {
        int n = r * 256 + tid;
        bool act = false;
        float4 cwv = make_float4(0.f, 0.f, 0.f, 0.f);
        int pack = 0;
        if (n < N_) {
            float relx = (fpv[r].x - cx) * (1.0f / 1.5f);
            float rely = (fpv[r].y - cy) * (1.0f / 1.5f);
            float r2 = relx * relx + rely * rely;
            float s  = 1.0f - r2;
            if (s > 0.0f) {
                float att = s * s * s * mkv[r];
                float rr;
                asm("sqrt.approx.f32 %0, %1;" : "=f"(rr) : "f"(r2 + 1e-9f));
                // theta/pi via octant-reduced poly
                float ax = fabsf(relx), ay = fabsf(rely);
                float mx = fmaxf(ax, ay), mn = fminf(ax, ay);
                float z  = (mx > 0.0f) ? __fdividef(mn, mx) : 0.0f;
                float z2 = z * z;
                float q = -0.0037310f;
                q = fmaf(q, z2,  0.0167600f);
                q = fmaf(q, z2, -0.0370620f);
                q = fmaf(q, z2,  0.0616061f);
                q = fmaf(q, z2, -0.1058772f);
                q = fmaf(q, z2,  0.3183026478f);
                q = q * z;                          // atan(z)/pi
                if (ay > ax)       q = 0.5f - q;
                if (relx < 0.0f)   q = 1.0f - q;
                q = copysignf(q, rely);             // theta/pi in [-1,1]
                float ix = 4.0f * rr - 0.5f;        // W=4
                float iy = fmaf(4.0f, q, 4.5f);     // H=10
                float x0f = floorf(ix), y0f = floorf(iy);
                float wx = ix - x0f;
                float wy = iy - y0f;
                int x0 = (int)x0f, y0 = (int)y0f;   // x0 in [-1,3], y0 in [0,8]
                float omx = 1.0f - wx, omy = 1.0f - wy;
                cwv.x = att * omx * omy;
                cwv.y = att * wx  * omy;
                cwv.z = att * omx * wy;
                cwv.w = att * wx  * wy;
                // pre-clamp: edge corners get zero weight AND a distinct dummy cell
                int xlo = x0, xhi = x0 + 1;
                if (x0 < 0)  { cwv.x = 0.f; cwv.z = 0.f; xlo = 1; }
                if (x0 >= 3) { cwv.y = 0.f; cwv.w = 0.f; xhi = 2; }
                pack = xlo | (xhi << 2) | (y0 << 4) | (n << 8);
                psi_part += att;
                act = (att != 0.0f);
            }
        }
        a_cw[r] = cwv; a_pk[r] = pack; a_act[r] = act;
        ballots[r] = __ballot_sync(0xffffffffu, act);
        if (lane == 0) wcnt[r * 8 + warp] = __popc(ballots[r]);
    }

    // psi warp-reduce
    #pragma unroll
    for (int o = 16; o; o >>= 1) psi_part += __shfl_xor_sync(0xffffffffu, psi_part, o);
    if (lane == 0) red[warp] = psi_part;
    __syncthreads();   // covers S-zeroing, wcnt, red

    // ---------- Phase A2: deterministic prefix + compacted write ----------
    int nact;
    {
        int tot = 0, base0 = 0, base1 = 0;
        #pragma unroll
        for (int s2 = 0; s2 < 16; ++s2) {
            if (s2 == warp)     base0 = tot;
            if (s2 == warp + 8) base1 = tot;
            tot += wcnt[s2];
        }
        nact = tot;
        unsigned lt = (1u << lane) - 1u;
        if (a_act[0]) {
            int idx = base0 + __popc(ballots[0] & lt);
            cw4[idx] = a_cw[0]; cpk[idx] = a_pk[0];
        }
        if (a_act[1]) {
            int idx = base1 + __popc(ballots[1] & lt);
            cw4[idx] = a_cw[1]; cpk[idx] = a_pk[1];
        }
        if (tid == 0) {
            float p = 0.f;
            #pragma unroll
            for (int w = 0; w < 8; ++w) p += red[w];
            shpsi[0] = (p == 0.0f) ? 1.0f : 1.0f / p;
        }
    }
    __syncthreads();

    // ---------- Phase B: scatter with depth-1 prefetch; single RMW per iter ----------
    // lane = corner(2b)*8 + pairi(3b): 32 distinct smem addrs per n (xlo != xhi
    // by construction). Loads for k+8 issue before the RMW of k so LDG latency
    // overlaps the LDS->FMA->STS chain. Clamped prefetch index, uniform control.
    {
        const int corner = lane >> 3;
        const int pairi  = lane & 7;
        const int xsh = (corner & 1) << 1;
        const int cby = corner >> 1;
        float* Smine = S + warp * 640;
        const float* cwf = (const float*)cw4;
        const float* featB = feat + (size_t)b * N_ * 16;

        int k = warp;
        if (k < nact) {
            float A  = cwf[k * 4 + corner];
            int   pk = cpk[k];
            float2 f = __ldg((const float2*)(featB + ((pk >> 4) & ~15) + pairi * 2));
            while (true) {
                int kn = k + 8;
                int kc = (kn < nact) ? kn : k;     // clamped prefetch
                float An  = cwf[kc * 4 + corner];
                int   pkn = cpk[kc];
                float2 fn = __ldg((const float2*)(featB + ((pkn >> 4) & ~15) + pairi * 2));
                // RMW for k
                int xi = (pk >> xsh) & 3;
                int yi = ((pk >> 4) & 15) + cby;
                float* sp = Smine + (yi * 4 + xi) * 16 + pairi * 2;
                float2 sv = *(float2*)sp;
                sv.x = fmaf(A, f.x, sv.x);
                sv.y = fmaf(A, f.y, sv.y);
                *(float2*)sp = sv;
                if (kn >= nact) break;
                A = An; pk = pkn; f = fn; k = kn;
            }
        }
    }
    __syncthreads();

    // ---------- Phase C1': reduce 8 copies + theta-wrap fold -> padded Sfold ----------
    // (Sfold aliases the cw region — dead after Phase B, barrier above orders it.)
    // 256 threads, one float2 each: e = (t(8), w(4), cpair(8)).
    // Sfold[comp*33 + t*4 + w]; wrap rows h=9 -> t=0, h=0 -> t=7.
    {
        const float2* S2 = (const float2*)S;
        int e = tid;
        int cpair = e & 7;
        int w  = (e >> 3) & 3;
        int t  = e >> 5;
        int src = ((t + 1) * 4 + w) * 8 + cpair;
        float2 a = S2[src];
        #pragma unroll
        for (int c = 1; c < 8; ++c) {
            float2 v = S2[c * 320 + src];
            a.x += v.x; a.y += v.y;
        }
        if (t == 0) {
            int sw = (9 * 4 + w) * 8 + cpair;
            #pragma unroll
            for (int c = 0; c < 8; ++c) {
                float2 v = S2[c * 320 + sw];
                a.x += v.x; a.y += v.y;
            }
        }
        if (t == 7) {
            int sw = (0 * 4 + w) * 8 + cpair;
            #pragma unroll
            for (int c = 0; c < 8; ++c) {
                float2 v = S2[c * 320 + sw];
                a.x += v.x; a.y += v.y;
            }
        }
        int tw = t * 4 + w;
        Sfold[(cpair * 2 + 0) * 33 + tw] = a.x;
        Sfold[(cpair * 2 + 1) * 33 + tw] = a.y;
    }
    __syncthreads();

    // ---------- Phase C2: out[o,y] = sum kern[o,i,w,t,y,x] * Sfold[i,x][t,w] ----------
    // warp = o; lane = t*4 + y*2 + x. kern: 32 coalesced LDG.32 (1 line each).
    // Sfold LDS: addr = (2i+x)*33 + 4t + w -> banks (x+4t)%32: conflict-free.
    {
        const int t = lane >> 2;
        const int x = lane & 1;
        const float* kb = kern + warp * 1024;
        float acc = 0.f;
        #pragma unroll
        for (int i = 0; i < 8; ++i) {
            const float* sfr = Sfold + (i * 2 + x) * 33 + t * 4;
            #pragma unroll
            for (int w = 0; w < 4; ++w) {
                float kv = __ldg(kb + i * 128 + w * 32 + lane);
                acc = fmaf(kv, sfr[w], acc);
            }
        }
        acc += __shfl_xor_sync(0xffffffffu, acc, 1);
        acc += __shfl_xor_sync(0xffffffffu, acc, 4);
        acc += __shfl_xor_sync(0xffffffffu, acc, 8);
        acc += __shfl_xor_sync(0xffffffffu, acc, 16);
        if ((lane & ~2u) == 0) {   // lanes 0 (y=0) and 2 (y=1)
            out[bm * 16 + warp * 2 + (lane >> 1)] = acc * shpsi[0];
        }
    }
}

extern "C" void kernel_launch(void* const* d_in, const int* in_sizes, int n_in,
                              void* d_out, int out_size)
{
    const float* field  = (const float*)d_in[0];
    const float* center = (const float*)d_in[1];
    const float* feat   = (const float*)d_in[2];
    const float* mask   = (const float*)d_in[3];
    const float* kern   = (const float*)d_in[4];
    float* out = (float*)d_out;

    cudaFuncSetAttribute(equi_cts_conv_kernel,
                         cudaFuncAttributeMaxDynamicSharedMemorySize, SMEM_BYTES);
    equi_cts_conv_kernel<<<B_ * M_, 256, SMEM_BYTES>>>(field, center, feat, mask, kern, out);
}

// round 16
// speedup vs baseline: 1.3789x; 1.0059x over previous
#include <cuda_runtime.h>
#include <math.h>

#define B_ 2
#define M_ 384
#define N_ 384

// Shared-memory layout (float offsets)
#define OFF_S     0        // 8 copies * 640 = 5120
#define OFF_CWP   5120     // 384 * 4 corners * float2{A, packed} = 3072
#define OFF_SFOLD OFF_CWP  // 528 floats, alias: cwp dead after Phase B
#define OFF_RED   8192     // 8 (psi warp partials)
#define OFF_PSI   8200     // 1 (reciprocal)
#define SMEM_FLOATS 8204
#define SMEM_BYTES  (SMEM_FLOATS * 4)   // 32816 B -> 6 blocks/SM (one wave)

__global__ __launch_bounds__(256, 6)
void equi_cts_conv_kernel(const float* __restrict__ field,
                          const float* __restrict__ center,
                          const float* __restrict__ feat,
                          const float* __restrict__ mask,
                          const float* __restrict__ kern,
                          float* __restrict__ out)
{
    extern __shared__ float sm[];
    float*  S     = sm + OFF_S;
    float4* cwp4  = (float4*)(sm + OFF_CWP);   // [idx][2]: (A0,p0,A1,p1),(A2,p2,A3,p3)
    float2* cwp2  = (float2*)(sm + OFF_CWP);   // [idx*4 + corner]
    float*  Sfold = sm + OFF_SFOLD;            // valid only after Phase-B barrier
    float*  red   = sm + OFF_RED;
    float*  shpsi = sm + OFF_PSI;
    __shared__ int wcnt[16];

    const int tid  = threadIdx.x;
    const int lane = tid & 31;
    const int warp = tid >> 5;
    const int bm   = blockIdx.x;
    const int b    = bm / M_;

    const float cx = center[bm * 2 + 0];
    const float cy = center[bm * 2 + 1];

    // ---------- Phase 0: zero S copies ----------
    {
        float4 z = make_float4(0.f, 0.f, 0.f, 0.f);
        float4* S4 = (float4*)S;
        #pragma unroll
        for (int i = tid; i < 1280; i += 256) S4[i] = z;
    }

    // ---------- Phase A1: geometry + corner weights + ballots ----------
    float2 fpv[2];
    float  mkv[2];
    {
        const float2* fB = (const float2*)(field + (size_t)b * N_ * 2);
        const float*  mB = mask + (size_t)b * N_;
        fpv[0] = fB[tid];
        fpv[1] = fB[256 + tid >= N_ ? tid : 256 + tid];
        mkv[0] = mB[tid];
        mkv[1] = mB[256 + tid >= N_ ? tid : 256 + tid];
    }

    float psi_part = 0.f;
    unsigned ballots[2];
    float4 a_cw[2];
    int    a_pk[2];
    bool   a_act[2];
    #pragma unroll
    for (int r = 0; r < 2; ++r) {
        int n = r * 256 + tid;
        bool act = false;
        float4 cwv = make_float4(0.f, 0.f, 0.f, 0.f);
        int pack = 0;
        if (n < N_) {
            float relx = (fpv[r].x - cx) * (1.0f / 1.5f);
            float rely = (fpv[r].y - cy) * (1.0f / 1.5f);
            float r2 = relx * relx + rely * rely;
            float s  = 1.0f - r2;
            if (s > 0.0f) {
                float att = s * s * s * mkv[r];
                float rr;
                asm("sqrt.approx.f32 %0, %1;" : "=f"(rr) : "f"(r2 + 1e-9f));
                // theta/pi via octant-reduced poly
                float ax = fabsf(relx), ay = fabsf(rely);
                float mx = fmaxf(ax, ay), mn = fminf(ax, ay);
                float z  = (mx > 0.0f) ? __fdividef(mn, mx) : 0.0f;
                float z2 = z * z;
                float q = -0.0037310f;
                q = fmaf(q, z2,  0.0167600f);
                q = fmaf(q, z2, -0.0370620f);
                q = fmaf(q, z2,  0.0616061f);
                q = fmaf(q, z2, -0.1058772f);
                q = fmaf(q, z2,  0.3183026478f);
                q = q * z;                          // atan(z)/pi
                if (ay > ax)       q = 0.5f - q;
                if (relx < 0.0f)   q = 1.0f - q;
                q = copysignf(q, rely);             // theta/pi in [-1,1]
                float ix = 4.0f * rr - 0.5f;        // W=4
                float iy = fmaf(4.0f, q, 4.5f);     // H=10
                float x0f = floorf(ix), y0f = floorf(iy);
                float wx = ix - x0f;
                float wy = iy - y0f;
                int x0 = (int)x0f, y0 = (int)y0f;   // x0 in [-1,3], y0 in [0,8]
                float omx = 1.0f - wx, omy = 1.0f - wy;
                cwv.x = att * omx * omy;
                cwv.y = att * wx  * omy;
                cwv.z = att * omx * wy;
                cwv.w = att * wx  * wy;
                // pre-clamp: edge corners get zero weight AND a distinct dummy cell
                int xlo = x0, xhi = x0 + 1;
                if (x0 < 0)  { cwv.x = 0.f; cwv.z = 0.f; xlo = 1; }
                if (x0 >= 3) { cwv.y = 0.f; cwv.w = 0.f; xhi = 2; }
                pack = xlo | (xhi << 2) | (y0 << 4) | (n << 8);
                psi_part += att;
                act = (att != 0.0f);
            }
        }
        a_cw[r] = cwv; a_pk[r] = pack; a_act[r] = act;
        ballots[r] = __ballot_sync(0xffffffffu, act);
        if (lane == 0) wcnt[r * 8 + warp] = __popc(ballots[r]);
    }

    // psi warp-reduce
    #pragma unroll
    for (int o = 16; o; o >>= 1) psi_part += __shfl_xor_sync(0xffffffffu, psi_part, o);
    if (lane == 0) red[warp] = psi_part;
    __syncthreads();   // covers S-zeroing, wcnt, red

    // ---------- Phase A2: prefix + fully-decoded per-(n,corner) records ----------
    // record[corner] = {A_corner, cell*16 | (n*16)<<13}
    int nact;
    {
        int tot = 0, base0 = 0, base1 = 0;
        #pragma unroll
        for (int s2 = 0; s2 < 16; ++s2) {
            if (s2 == warp)     base0 = tot;
            if (s2 == warp + 8) base1 = tot;
            tot += wcnt[s2];
        }
        nact = tot;
        unsigned lt = (1u << lane) - 1u;
        #pragma unroll
        for (int r = 0; r < 2; ++r) {
            if (a_act[r]) {
                int idx = (r ? base1 : base0) + __popc(ballots[r] & lt);
                int pk  = a_pk[r];
                int xlo = pk & 3, xhi = (pk >> 2) & 3;
                int y0  = (pk >> 4) & 15;
                int nf  = (pk >> 8) << 4;            // n*16
                int hi  = nf << 13;
                int rlo = y0 * 64, rhi = rlo + 64;   // y*4*16
                float4 w4 = a_cw[r];
                cwp4[idx * 2 + 0] = make_float4(
                    w4.x, __int_as_float(hi | (rlo + xlo * 16)),
                    w4.y, __int_as_float(hi | (rlo + xhi * 16)));
                cwp4[idx * 2 + 1] = make_float4(
                    w4.z, __int_as_float(hi | (rhi + xlo * 16)),
                    w4.w, __int_as_float(hi | (rhi + xhi * 16)));
            }
        }
        if (tid == 0) {
            float p = 0.f;
            #pragma unroll
            for (int w = 0; w < 8; ++w) p += red[w];
            shpsi[0] = (p == 0.0f) ? 1.0f : 1.0f / p;
        }
    }
    __syncthreads();

    // ---------- Phase B: scatter; pre-decoded records, depth-1 prefetch ----------
    // lane = corner(2b)*8 + pairi(3b): 32 distinct smem addrs per n.
    // Record LDS.64: 4 distinct 8B addrs per warp (banks corner*2) -> multicast.
    {
        const int corner = lane >> 3;
        const int pairi  = lane & 7;
        const int p2 = pairi * 2;
        float* Smine = S + warp * 640;
        const float* featB = feat + (size_t)b * N_ * 16 + p2;

        int k = warp;
        if (k < nact) {
            float2 e = cwp2[k * 4 + corner];
            int  pe  = __float_as_int(e.y);
            float2 f = __ldg((const float2*)(featB + (pe >> 13)));
            while (true) {
                int kn = k + 8;
                int kc = (kn < nact) ? kn : k;     // clamped prefetch
                float2 en = cwp2[kc * 4 + corner];
                int  pen  = __float_as_int(en.y);
                float2 fn = __ldg((const float2*)(featB + (pen >> 13)));
                // RMW for k
                float* sp = Smine + (pe & 8191) + p2;
                float2 sv = *(float2*)sp;
                sv.x = fmaf(e.x, f.x, sv.x);
                sv.y = fmaf(e.x, f.y, sv.y);
                *(float2*)sp = sv;
                if (kn >= nact) break;
                e = en; pe = pen; f = fn; k = kn;
            }
        }
    }
    __syncthreads();

    // ---------- Phase C1': reduce 8 copies + theta-wrap fold -> padded Sfold ----------
    // (Sfold aliases cwp — dead after Phase B.) e = (t(8), w(4), cpair(8)).
    // Sfold[comp*33 + t*4 + w]; wrap rows h=9 -> t=0, h=0 -> t=7.
    {
        const float2* S2 = (const float2*)S;
        int e = tid;
        int cpair = e & 7;
        int w  = (e >> 3) & 3;
        int t  = e >> 5;
        int src = ((t + 1) * 4 + w) * 8 + cpair;
        float2 a = S2[src];
        #pragma unroll
        for (int c = 1; c < 8; ++c) {
            float2 v = S2[c * 320 + src];
            a.x += v.x; a.y += v.y;
        }
        if (t == 0) {
            int sw = (9 * 4 + w) * 8 + cpair;
            #pragma unroll
            for (int c = 0; c < 8; ++c) {
                float2 v = S2[c * 320 + sw];
                a.x += v.x; a.y += v.y;
            }
        }
        if (t == 7) {
            int sw = (0 * 4 + w) * 8 + cpair;
            #pragma unroll
            for (int c = 0; c < 8; ++c) {
                float2 v = S2[c * 320 + sw];
                a.x += v.x; a.y += v.y;
            }
        }
        int tw = t * 4 + w;
        Sfold[(cpair * 2 + 0) * 33 + tw] = a.x;
        Sfold[(cpair * 2 + 1) * 33 + tw] = a.y;
    }
    __syncthreads();

    // ---------- Phase C2: out[o,y] = sum kern[o,i,w,t,y,x] * Sfold[i,x][t,w] ----------
    // warp = o; lane = t*4 + y*2 + x. kern: 32 coalesced LDG.32.
    // Sfold LDS: addr = (2i+x)*33 + 4t + w -> banks (x+4t)%32: conflict-free.
    {
        const int t = lane >> 2;
        const int x = lane & 1;
        const float* kb = kern + warp * 1024;
        float acc = 0.f;
        #pragma unroll
        for (int i = 0; i < 8; ++i) {
            const float* sfr = Sfold + (i * 2 + x) * 33 + t * 4;
            #pragma unroll
            for (int w = 0; w < 4; ++w) {
                float kv = __ldg(kb + i * 128 + w * 32 + lane);
                acc = fmaf(kv, sfr[w], acc);
            }
        }
        acc += __shfl_xor_sync(0xffffffffu, acc, 1);
        acc += __shfl_xor_sync(0xffffffffu, acc, 4);
        acc += __shfl_xor_sync(0xffffffffu, acc, 8);
        acc += __shfl_xor_sync(0xffffffffu, acc, 16);
        if ((lane & ~2u) == 0) {   // lanes 0 (y=0) and 2 (y=1)
            out[bm * 16 + warp * 2 + (lane >> 1)] = acc * shpsi[0];
        }
    }
}

extern "C" void kernel_launch(void* const* d_in, const int* in_sizes, int n_in,
                              void* d_out, int out_size)
{
    const float* field  = (const float*)d_in[0];
    const float* center = (const float*)d_in[1];
    const float* feat   = (const float*)d_in[2];
    const float* mask   = (const float*)d_in[3];
    const float* kern   = (const float*)d_in[4];
    float* out = (float*)d_out;

    cudaFuncSetAttribute(equi_cts_conv_kernel,
                         cudaFuncAttributeMaxDynamicSharedMemorySize, SMEM_BYTES);
    equi_cts_conv_kernel<<<B_ * M_, 256, SMEM_BYTES>>>(field, center, feat, mask, kern, out);
}